// round 16
// baseline (speedup 1.0000x reference)
#include <cuda_runtime.h>

#define BB 16
#define KK 4096
#define CC 256
#define PP 1024
#define SS 16
#define HH 128
#define NROWS (BB*PP*SS)   // 262144
#define NPQ   (BB*PP)      // 16384
#define OUTC  22

typedef unsigned long long u64;

// ------------- static device scratch (no allocations allowed) -------------
__device__ __align__(16) float g_new_xyz[NPQ*3];
__device__ int   g_gidx[NROWS];
__device__ __align__(16) float g_gxyz[NROWS*3];
__device__ __align__(16) float g_w0fT[CC*HH];
__device__ __align__(16) float g_wT[4][HH*HH];     // w1m,w2m,w1f,w2f  (k-major)
__device__ __align__(16) float g_wTh[2][HH*HH];    // tf32-hi of w1m,w2m (k-major)
__device__ __align__(16) float g_wTl[2][HH*HH];    // tf32-lo of w1m,w2m
__device__ __align__(16) float g_F0[BB*KK*HH];     // 33.5 MB (L2-resident)
__device__ __align__(16) float g_zA[(size_t)NROWS*HH]; // 134 MB (z1)
__device__ __align__(16) float g_agg[NPQ*HH];
__device__ __align__(16) float g_f1[NPQ*HH];
__device__ __align__(16) float g_f2[NPQ*HH];
__device__ __align__(16) float g_psum[4096*HH];
__device__ __align__(16) float g_psq[4096*HH];
__device__ float g_scale[5][HH];
__device__ float g_shift[5][HH];

__device__ __forceinline__ u64 pack2(float lo, float hi){
    u64 r; asm("mov.b64 %0, {%1, %2};" : "=l"(r) : "f"(lo), "f"(hi)); return r;
}
__device__ __forceinline__ void unpack2(u64 v, float& lo, float& hi){
    asm("mov.b64 {%0, %1}, %2;" : "=f"(lo), "=f"(hi) : "l"(v));
}
__device__ __forceinline__ void fma2(u64& d, u64 a, u64 b){
    asm("fma.rn.f32x2 %0, %1, %2, %0;" : "+l"(d) : "l"(a), "l"(b));
}
__device__ __forceinline__ u64 add2(u64 a, u64 b){
    u64 r; asm("add.rn.f32x2 %0, %1, %2;" : "=l"(r) : "l"(a), "l"(b)); return r;
}
__device__ __forceinline__ u64 mul2(u64 a, u64 b){
    u64 r; asm("mul.rn.f32x2 %0, %1, %2;" : "=l"(r) : "l"(a), "l"(b)); return r;
}
__device__ __forceinline__ unsigned to_tf32(float x){
    unsigned r; asm("cvt.rna.tf32.f32 %0, %1;" : "=r"(r) : "f"(x)); return r;
}
__device__ __forceinline__ void mma_tf32(float* d, const unsigned* a, unsigned b0, unsigned b1){
    asm volatile("mma.sync.aligned.m16n8k8.row.col.f32.tf32.tf32.f32 "
        "{%0,%1,%2,%3}, {%4,%5,%6,%7}, {%8,%9}, {%0,%1,%2,%3};"
        : "+f"(d[0]), "+f"(d[1]), "+f"(d[2]), "+f"(d[3])
        : "r"(a[0]), "r"(a[1]), "r"(a[2]), "r"(a[3]), "r"(b0), "r"(b1));
}

// ------------- prep: weight transposes + tf32 split of big-layer weights ---
__global__ void prep_kernel(const float* __restrict__ w0,
                            const float* __restrict__ w1m, const float* __restrict__ w2m,
                            const float* __restrict__ w1f, const float* __restrict__ w2f)
{
    int tid = blockIdx.x*blockDim.x + threadIdx.x;
    if(tid < CC*HH){
        int c = tid >> 7, o = tid & 127;
        g_w0fT[tid] = w0[o*259 + 3 + c];
    }
    int r = tid - CC*HH;
    if(r >= 0 && r < 4*HH*HH){
        int m = r >> 14;
        int e = r & (HH*HH-1);
        int c = e >> 7, o = e & 127;
        const float* src = (m==0)?w1m:(m==1)?w2m:(m==2)?w1f:w2f;
        float v = src[o*HH + c];
        g_wT[m][c*HH + o] = v;
        if(m < 2){
            float hi = __uint_as_float(to_tf32(v));
            float lo = v - hi;
            g_wTh[m][c*HH + o] = hi;
            g_wTl[m][c*HH + o] = __uint_as_float(to_tf32(lo));
        }
    }
}

// profiler-steering no-op (keeps ncu -s 5 on gemm_tc<true>)
__global__ void nudge_kernel(){}

// ------------- FPS: exact serial farthest point, f32x2 dist ----------------
__device__ void fps_dev(const float* __restrict__ xyz, int b)
{
    extern __shared__ float dynsm[];
    float* sc = dynsm;                       // 12288 floats: coords
    u64*  swk = (u64*)(dynsm + 12288);       // 16 key slots (2 x 8 warps)
    int t = threadIdx.x, lane = t & 31, w = t >> 5;
    const float* px = xyz + (size_t)b*KK*3;
    for(int i=t; i<3072; i+=256) ((float4*)sc)[i] = ((const float4*)px)[i];
    __syncthreads();
    u64 X2[8], Y2[8], Z2[8];
    float D[16];
#pragma unroll
    for(int p=0;p<8;p++){
        int i0 = (2*p)*256 + t, i1 = i0 + 256;
        X2[p] = pack2(sc[i0*3+0], sc[i1*3+0]);
        Y2[p] = pack2(sc[i0*3+1], sc[i1*3+1]);
        Z2[p] = pack2(sc[i0*3+2], sc[i1*3+2]);
    }
#pragma unroll
    for(int j=0;j<16;j++) D[j] = 1e10f;
    float cx = sc[0], cy = sc[1], cz = sc[2];
    if(t==0){
        int o = b*PP*3;
        g_new_xyz[o+0]=cx; g_new_xyz[o+1]=cy; g_new_xyz[o+2]=cz;
    }
    for(int it=1; it<PP; it++){
        u64 nx2 = pack2(-cx,-cx), ny2 = pack2(-cy,-cy), nz2 = pack2(-cz,-cz);
        float bd = -1.0f; int bi = 0;
#pragma unroll
        for(int p=0;p<8;p++){
            u64 dx2 = add2(X2[p], nx2);
            u64 dy2 = add2(Y2[p], ny2);
            u64 dz2 = add2(Z2[p], nz2);
            u64 s2 = add2(add2(mul2(dx2,dx2), mul2(dy2,dy2)), mul2(dz2,dz2));
            float d0, d1; unpack2(s2, d0, d1);
            float dm0 = fminf(D[2*p], d0);   D[2*p]   = dm0;
            if(dm0 > bd){ bd = dm0; bi = (2*p)*256 + t; }
            float dm1 = fminf(D[2*p+1], d1); D[2*p+1] = dm1;
            if(dm1 > bd){ bd = dm1; bi = (2*p+1)*256 + t; }
        }
        unsigned db = __float_as_uint(bd);               // bd >= 0
        unsigned mx = __reduce_max_sync(0xFFFFFFFFu, db);
        unsigned cand = (db == mx) ? (unsigned)bi : 0xFFFFFFFFu;
        unsigned mn = __reduce_min_sync(0xFFFFFFFFu, cand);   // lowest idx on ties
        if(lane == 0) swk[(it & 1)*8 + w] = ((u64)mx << 32) | (u64)(0xFFFFFFFFu - mn);
        __syncthreads();
        u64 win = swk[(it & 1)*8];
#pragma unroll
        for(int k=1;k<8;k++){
            u64 o = swk[(it & 1)*8 + k];
            win = (win > o) ? win : o;
        }
        int cur = (int)(0xFFFFFFFFu - (unsigned)(win & 0xFFFFFFFFull));
        cx = sc[cur*3+0]; cy = sc[cur*3+1]; cz = sc[cur*3+2];
        if(t == 0){
            int o = (b*PP + it)*3;
            g_new_xyz[o+0]=cx; g_new_xyz[o+1]=cy; g_new_xyz[o+2]=cz;
        }
    }
}

// ------------- gemmF0 device func: F0 = features^T @ W0feat^T (f32x2) -------
__device__ void gemmF0_dev(const float* __restrict__ feats, int id)
{
    extern __shared__ float dynsm[];
    float* As = dynsm;            // 16*128
    float* Bs = dynsm + 2048;     // 16*128
    int bx = id & 31, b = id >> 5;
    int m0 = bx * 128;
    const float* A = feats + (size_t)b*CC*KK;
    int t = threadIdx.x, tx = t & 15, ty = t >> 4;
    u64 acc[8][4];
#pragma unroll
    for(int i=0;i<8;i++)
#pragma unroll
        for(int j=0;j<4;j++) acc[i][j]=0ull;

    for(int k0=0;k0<CC;k0+=16){
#pragma unroll
        for(int q=0;q<2;q++){
            int v = q*256 + t;
            int c = v >> 5, m4 = v & 31;
            *(float4*)(As + c*128 + m4*4) =
                *(const float4*)(A + (size_t)(k0+c)*KK + m0 + m4*4);
        }
#pragma unroll
        for(int q=0;q<2;q++){
            int v = q*256 + t;
            int kr = v >> 5, o4 = v & 31;
            *(float4*)(Bs + kr*128 + o4*4) =
                *(const float4*)(g_w0fT + (k0+kr)*128 + o4*4);
        }
        __syncthreads();
#pragma unroll
        for(int k=0;k<16;k++){
            float a[8];
            *(float4*)(a)    = *(float4*)(As + k*128 + ty*8);
            *(float4*)(a+4)  = *(float4*)(As + k*128 + ty*8 + 4);
            ulonglong2 bl0 = *(const ulonglong2*)(Bs + k*128 + tx*8);
            ulonglong2 bl1 = *(const ulonglong2*)(Bs + k*128 + tx*8 + 4);
            u64 b2[4] = {bl0.x, bl0.y, bl1.x, bl1.y};
#pragma unroll
            for(int i=0;i<8;i++){
                u64 a2 = pack2(a[i], a[i]);
#pragma unroll
                for(int j=0;j<4;j++) fma2(acc[i][j], a2, b2[j]);
            }
        }
        __syncthreads();
    }
#pragma unroll
    for(int i=0;i<8;i++){
        float f[8];
#pragma unroll
        for(int j=0;j<4;j++) unpack2(acc[i][j], f[2*j], f[2*j+1]);
        size_t row = (size_t)b*KK + m0 + ty*8 + i;
        *(float4*)(g_F0 + row*HH + tx*8)     = make_float4(f[0],f[1],f[2],f[3]);
        *(float4*)(g_F0 + row*HH + tx*8 + 4) = make_float4(f[4],f[5],f[6],f[7]);
    }
}

// ------------- combo: blocks 0..15 = FPS, 16..527 = gemmF0 (overlap) -------
__global__ void __launch_bounds__(256,1) combo_kernel(const float* __restrict__ xyz,
                                                      const float* __restrict__ feats)
{
    if(blockIdx.x < 16) fps_dev(xyz, blockIdx.x);
    else                gemmF0_dev(feats, blockIdx.x - 16);
}

// ---- fused ballquery + stats0: 32 queries/block, xyz staged in smem ----
__global__ void __launch_bounds__(256) bqstats_kernel(const float* __restrict__ xyz,
                                                      const float* __restrict__ w0)
{
    extern __shared__ float bsm[];
    float* sxyz = bsm;                       // 12288 floats
    int*   sidx = (int*)(bsm + 12288);       // 512
    float* sgx  = bsm + 12288 + 512;         // 512
    float* sgy  = sgx + 512;
    float* sgz  = sgy + 512;
    int t = threadIdx.x, lane = t & 31, w = t >> 5;
    int q0 = blockIdx.x * 32;
    int b  = q0 >> 10;
    const float* px = xyz + (size_t)b*KK*3;
    for(int i=t; i<3072; i+=256) ((float4*)sxyz)[i] = ((const float4*)px)[i];
    __syncthreads();

#pragma unroll
    for(int j=0;j<4;j++){
        int q = q0 + w*4 + j;
        float qx = g_new_xyz[q*3+0];
        float qy = g_new_xyz[q*3+1];
        float qz = g_new_xyz[q*3+2];
        int* out = g_gidx + q*SS;
        int count = 0;
        int firstidx = -1;
        for(int base=0; base<KK; base+=32){
            int i = base + lane;
            float dx = __fsub_rn(sxyz[i*3+0], qx);
            float dy = __fsub_rn(sxyz[i*3+1], qy);
            float dz = __fsub_rn(sxyz[i*3+2], qz);
            float d  = __fadd_rn(__fadd_rn(__fmul_rn(dx,dx), __fmul_rn(dy,dy)), __fmul_rn(dz,dz));
            bool in = d < 0.09f;
            unsigned m = __ballot_sync(0xFFFFFFFFu, in);
            if(in){
                int pos = count + __popc(m & ((1u << lane) - 1u));
                if(pos < SS) out[pos] = i;
                if(pos == 0) firstidx = i;
            }
            count += __popc(m);
            if(count >= SS) break;
        }
        if(count < SS){
            int f = __reduce_max_sync(0xFFFFFFFFu, firstidx);
            if(f < 0) f = KK-1;
            for(int jj = count + lane; jj < SS; jj += 32) out[jj] = f;
        }
    }
    __syncthreads();

    for(int rr = t; rr < 512; rr += 256){
        int n   = q0*16 + rr;
        int idx = g_gidx[n];
        int qq  = n >> 4;
        float gx = __fdiv_rn(__fsub_rn(sxyz[idx*3+0], g_new_xyz[qq*3+0]), 0.3f);
        float gy = __fdiv_rn(__fsub_rn(sxyz[idx*3+1], g_new_xyz[qq*3+1]), 0.3f);
        float gz = __fdiv_rn(__fsub_rn(sxyz[idx*3+2], g_new_xyz[qq*3+2]), 0.3f);
        sidx[rr]=idx; sgx[rr]=gx; sgy[rr]=gy; sgz[rr]=gz;
        g_gxyz[n*3+0]=gx; g_gxyz[n*3+1]=gy; g_gxyz[n*3+2]=gz;
    }
    __syncthreads();
    int h = t >> 7, ch = t & 127;
    float wx = w0[ch*259+0], wy = w0[ch*259+1], wz = w0[ch*259+2];
    float ls = 0.f, lq = 0.f;
    const float* F0b = g_F0 + (size_t)b*KK*HH;
    for(int r=0;r<256;r++){
        int rr = h*256 + r;
        float v = F0b[(size_t)sidx[rr]*HH + ch];
        v = fmaf(sgx[rr], wx, fmaf(sgy[rr], wy, fmaf(sgz[rr], wz, v)));
        ls += v;
        lq = fmaf(v, v, lq);
    }
    g_psum[(blockIdx.x*2 + h)*128 + ch] = ls;
    g_psq [(blockIdx.x*2 + h)*128 + ch] = lq;
}

// ------------- finalize BN stats -> (scale, shift); 1 block per channel ----
__global__ void finalize_kernel(int layer, int count, double n,
                                const float* __restrict__ g, const float* __restrict__ be)
{
    __shared__ double ss[256], sq[256];
    int c = blockIdx.x;
    int t = threadIdx.x;
    double s = 0.0, q = 0.0;
    for(int i=t; i<count; i+=256){
        s += (double)g_psum[i*128 + c];
        q += (double)g_psq [i*128 + c];
    }
    ss[t] = s; sq[t] = q;
    __syncthreads();
#pragma unroll
    for(int off=128; off; off>>=1){
        if(t < off){ ss[t] += ss[t+off]; sq[t] += sq[t+off]; }
        __syncthreads();
    }
    if(t == 0){
        double mean = ss[0] / n;
        double var  = sq[0] / n - mean*mean;
        double rs   = 1.0 / sqrt(var + 1e-5);
        float sc = g[c] * (float)rs;
        g_scale[layer][c] = sc;
        g_shift[layer][c] = be[c] - (float)mean * sc;
    }
}

// ---- big GEMM via 3xTF32 mma.sync: 128x128 block, 8 warps (4M x 2N).
// A staged in packed fragment layout: per (m16,k8) tile a 256-float region of
// 64 float4-slots. Lane's fragment = slots (lane*2+j), stored at slot^((slot>>3)&1)
// (involution -> bijective, no collisions; all LDS.128 phases conflict-free).
// Slot content: {hi(p0),lo(p0),hi(p1),lo(p1)} for j=0, {p2,p3} for j=1, where
// p = (r16>>3) + 2*(kk>>2) matches mma fragment order a0..a3.
template<bool GATHER>
__global__ void __launch_bounds__(256,2) gemm_tc_kernel(const float* __restrict__ w0, int w_sel, int nl)
{
    __shared__ float AF[16*256];             // 8 m-tiles x 2 k8-tiles, 256 floats each
    __shared__ float Bh[16*136], Bl[16*136];
    __shared__ float s_sc[HH], s_sh[HH];
    __shared__ float sw0[3*HH];
    __shared__ int   sidx[128];
    __shared__ float sgx[128], sgy[128], sgz[128];
    const float* Wh = g_wTh[w_sel];
    const float* Wl = g_wTl[w_sel];
    int t = threadIdx.x;
    int lane = t & 31, warp = t >> 5;
    int wm = warp & 3, wn = warp >> 2;
    int m0 = blockIdx.x * 128;
    if(t < HH){
        s_sc[t] = g_scale[nl][t];
        s_sh[t] = g_shift[nl][t];
        if(GATHER){
            sw0[t]       = w0[t*259+0];
            sw0[HH+t]    = w0[t*259+1];
            sw0[2*HH+t]  = w0[t*259+2];
        }
    }
    if(GATHER && t < 128){
        int r = m0 + t;
        sidx[t] = g_gidx[r];
        sgx[t] = g_gxyz[r*3+0];
        sgy[t] = g_gxyz[r*3+1];
        sgz[t] = g_gxyz[r*3+2];
    }
    float acc[2][8][4];
#pragma unroll
    for(int i=0;i<2;i++)
#pragma unroll
        for(int j=0;j<8;j++)
#pragma unroll
            for(int k=0;k<4;k++) acc[i][j][k]=0.f;
    __syncthreads();

    int b = m0 >> 14;
    const float* F0b = g_F0 + (size_t)b*KK*HH;

    for(int k0=0;k0<HH;k0+=16){
        // stage A: 128 rows x 16 k -> packed fragment layout, split hi/lo
#pragma unroll
        for(int q=0;q<2;q++){
            int lin = q*256 + t;
            int row = lin >> 2, c4 = lin & 3, c = k0 + c4*4;
            float4 x;
            if(GATHER){
                x = *(const float4*)(F0b + (size_t)sidx[row]*HH + c);
                float gx = sgx[row], gy = sgy[row], gz = sgz[row];
                x.x = fmaf(gx, sw0[c+0], fmaf(gy, sw0[HH+c+0], fmaf(gz, sw0[2*HH+c+0], x.x)));
                x.y = fmaf(gx, sw0[c+1], fmaf(gy, sw0[HH+c+1], fmaf(gz, sw0[2*HH+c+1], x.y)));
                x.z = fmaf(gx, sw0[c+2], fmaf(gy, sw0[HH+c+2], fmaf(gz, sw0[2*HH+c+2], x.z)));
                x.w = fmaf(gx, sw0[c+3], fmaf(gy, sw0[HH+c+3], fmaf(gz, sw0[2*HH+c+3], x.w)));
            } else {
                x = *(const float4*)(g_zA + (size_t)(m0+row)*HH + c);
            }
            float xv[4];
            xv[0] = fmaxf(fmaf(x.x, s_sc[c+0], s_sh[c+0]), 0.f);
            xv[1] = fmaxf(fmaf(x.y, s_sc[c+1], s_sh[c+1]), 0.f);
            xv[2] = fmaxf(fmaf(x.z, s_sc[c+2], s_sh[c+2]), 0.f);
            xv[3] = fmaxf(fmaf(x.w, s_sc[c+3], s_sh[c+3]), 0.f);
            int r16 = row & 15, tm = row >> 4;
#pragma unroll
            for(int j=0;j<4;j++){
                float hi = __uint_as_float(to_tf32(xv[j]));
                float lo = xv[j] - hi;
                int kc = c4*4 + j;
                int k8 = kc >> 3, kk = kc & 7;
                int lf = (r16 & 7)*4 + (kk & 3);
                int p  = (r16 >> 3) + 2*(kk >> 2);
                int slot = lf*2 + (p >> 1);
                slot ^= (slot >> 3) & 1;
                int off = (tm*2 + k8)*256 + slot*4 + (p & 1)*2;
                *(float2*)(AF + off) = make_float2(hi, __uint_as_float(to_tf32(lo)));
            }
        }
        // stage B: 16 k x 128 n, pitch 136
#pragma unroll
        for(int q=0;q<2;q++){
            int lin = q*256 + t;
            int kr = lin >> 5, o4 = lin & 31;
            *(float4*)(Bh + kr*136 + o4*4) = *(const float4*)(Wh + (k0+kr)*HH + o4*4);
            *(float4*)(Bl + kr*136 + o4*4) = *(const float4*)(Wl + (k0+kr)*HH + o4*4);
        }
        __syncthreads();
        int s0 = lane*2;     s0 ^= (s0 >> 3) & 1;
        int s1 = lane*2 + 1; s1 ^= (s1 >> 3) & 1;
#pragma unroll
        for(int ks=0;ks<16;ks+=8){
            int k8 = ks >> 3;
            int ka = ks + (lane & 3);
            unsigned ah[2][4], al[2][4];
#pragma unroll
            for(int mt=0;mt<2;mt++){
                int tm = wm*2 + mt;
                int rbase = (tm*2 + k8)*256;
                float4 p0 = *(const float4*)(AF + rbase + s0*4);
                float4 p1 = *(const float4*)(AF + rbase + s1*4);
                ah[mt][0] = __float_as_uint(p0.x); al[mt][0] = __float_as_uint(p0.y);
                ah[mt][1] = __float_as_uint(p0.z); al[mt][1] = __float_as_uint(p0.w);
                ah[mt][2] = __float_as_uint(p1.x); al[mt][2] = __float_as_uint(p1.y);
                ah[mt][3] = __float_as_uint(p1.z); al[mt][3] = __float_as_uint(p1.w);
            }
#pragma unroll
            for(int nt=0;nt<8;nt++){
                int nc = wn*64 + nt*8 + (lane >> 2);
                unsigned bh0 = __float_as_uint(Bh[ka*136 + nc]);
                unsigned bh1 = __float_as_uint(Bh[(ka+4)*136 + nc]);
                unsigned bl0 = __float_as_uint(Bl[ka*136 + nc]);
                unsigned bl1 = __float_as_uint(Bl[(ka+4)*136 + nc]);
#pragma unroll
                for(int mt=0;mt<2;mt++){
                    mma_tf32(acc[mt][nt], ah[mt], bl0, bl1);
                    mma_tf32(acc[mt][nt], al[mt], bh0, bh1);
                    mma_tf32(acc[mt][nt], ah[mt], bh0, bh1);
                }
            }
        }
        __syncthreads();
    }

    int c0 = (lane & 3), rfrag = lane >> 2;
    if(GATHER){
#pragma unroll
        for(int mt=0;mt<2;mt++){
#pragma unroll
            for(int nt=0;nt<8;nt++){
                size_t rg = (size_t)m0 + wm*32 + mt*16 + rfrag;
                int col = wn*64 + nt*8 + 2*c0;
                *(float2*)(g_zA + rg*HH + col)        = make_float2(acc[mt][nt][0], acc[mt][nt][1]);
                *(float2*)(g_zA + (rg+8)*HH + col)    = make_float2(acc[mt][nt][2], acc[mt][nt][3]);
            }
        }
    } else {
#pragma unroll
        for(int mt=0;mt<2;mt++){
            float m0v[8], m1v[8];
#pragma unroll
            for(int nt=0;nt<8;nt++){
                m0v[nt] = fmaxf(acc[mt][nt][0], acc[mt][nt][2]);
                m1v[nt] = fmaxf(acc[mt][nt][1], acc[mt][nt][3]);
            }
#pragma unroll
            for(int off=4; off<32; off<<=1){
#pragma unroll
                for(int nt=0;nt<8;nt++){
                    m0v[nt] = fmaxf(m0v[nt], __shfl_xor_sync(0xFFFFFFFFu, m0v[nt], off));
                    m1v[nt] = fmaxf(m1v[nt], __shfl_xor_sync(0xFFFFFFFFu, m1v[nt], off));
                }
            }
            if(lane < 4){
                int q = (m0 + wm*32 + mt*16) >> 4;
#pragma unroll
                for(int nt=0;nt<8;nt++){
                    int col = wn*64 + nt*8 + 2*c0;
                    *(float2*)(g_agg + (size_t)q*HH + col) = make_float2(m0v[nt], m1v[nt]);
                }
            }
        }
    }

    // deterministic per-block column stats of raw C
    float cs[8][2], cq[8][2];
#pragma unroll
    for(int nt=0;nt<8;nt++){
#pragma unroll
        for(int p=0;p<2;p++){
            float a0 = acc[0][nt][p],   a1 = acc[0][nt][p+2];
            float a2 = acc[1][nt][p],   a3 = acc[1][nt][p+2];
            cs[nt][p] = ((a0 + a1) + (a2 + a3));
            cq[nt][p] = fmaf(a3,a3, fmaf(a2,a2, fmaf(a1,a1, a0*a0)));
        }
    }
#pragma unroll
    for(int off=4; off<32; off<<=1){
#pragma unroll
        for(int nt=0;nt<8;nt++){
#pragma unroll
            for(int p=0;p<2;p++){
                cs[nt][p] += __shfl_xor_sync(0xFFFFFFFFu, cs[nt][p], off);
                cq[nt][p] += __shfl_xor_sync(0xFFFFFFFFu, cq[nt][p], off);
            }
        }
    }
    float* red_s = Bh;   // reuse (>=512 floats)
    float* red_q = Bl;
    if(lane < 4){
#pragma unroll
        for(int nt=0;nt<8;nt++){
            int col = wn*64 + nt*8 + 2*lane;
            red_s[wm*128 + col]     = cs[nt][0];
            red_s[wm*128 + col + 1] = cs[nt][1];
            red_q[wm*128 + col]     = cq[nt][0];
            red_q[wm*128 + col + 1] = cq[nt][1];
        }
    }
    __syncthreads();
    if(t < 128){
        float s = ((red_s[t] + red_s[128+t]) + (red_s[256+t] + red_s[384+t]));
        float q = ((red_q[t] + red_q[128+t]) + (red_q[256+t] + red_q[384+t]));
        g_psum[blockIdx.x*128 + t] = s;
        g_psq [blockIdx.x*128 + t] = q;
    }
}

// ------------- small FC GEMM (NPQ rows): 128x128 tile, 8x8, f32x2 ----------
__device__ __forceinline__ float* selbuf(int s){
    switch(s){
        case 2: return g_agg;
        case 3: return g_f1;
        default: return g_f2;
    }
}
__global__ void __launch_bounds__(256,2) gemm128_kernel(int a_sel, int w_sel, int c_sel, int nl)
{
    __shared__ float As[16*132];
    __shared__ float Bs[16*128];
    __shared__ float s_sc[HH], s_sh[HH];
    const float* A = selbuf(a_sel);
    const float* W = g_wT[w_sel];
    float* Cm = selbuf(c_sel);
    int t = threadIdx.x;
    if(t < HH){
        s_sc[t] = g_scale[nl][t];
        s_sh[t] = g_shift[nl][t];
    }
    int m0 = blockIdx.x * 128;
    int tx = t & 15, ty = t >> 4;
    u64 acc[8][4];
#pragma unroll
    for(int i=0;i<8;i++)
#pragma unroll
        for(int j=0;j<4;j++) acc[i][j]=0ull;
    __syncthreads();

    for(int k0=0;k0<HH;k0+=16){
#pragma unroll
        for(int q=0;q<2;q++){
            int v = q*256 + t;
            int row = v >> 2, c4 = v & 3;
            float4 x = *(const float4*)(A + (size_t)(m0+row)*HH + k0 + c4*4);
            int cb = k0 + c4*4;
            x.x = fmaxf(fmaf(x.x, s_sc[cb+0], s_sh[cb+0]), 0.f);
            x.y = fmaxf(fmaf(x.y, s_sc[cb+1], s_sh[cb+1]), 0.f);
            x.z = fmaxf(fmaf(x.z, s_sc[cb+2], s_sh[cb+2]), 0.f);
            x.w = fmaxf(fmaf(x.w, s_sc[cb+3], s_sh[cb+3]), 0.f);
            As[(c4*4+0)*132 + row] = x.x;
            As[(c4*4+1)*132 + row] = x.y;
            As[(c4*4+2)*132 + row] = x.z;
            As[(c4*4+3)*132 + row] = x.w;
        }
#pragma unroll
        for(int q=0;q<2;q++){
            int v = q*256 + t;
            int kr = v >> 5, o4 = v & 31;
            *(float4*)(Bs + kr*128 + o4*4) =
                *(const float4*)(W + (k0+kr)*HH + o4*4);
        }
        __syncthreads();
#pragma unroll
        for(int k=0;k<16;k++){
            float a[8];
            *(float4*)(a)    = *(float4*)(As + k*132 + ty*8);
            *(float4*)(a+4)  = *(float4*)(As + k*132 + ty*8 + 4);
            ulonglong2 bl0 = *(const ulonglong2*)(Bs + k*128 + tx*8);
            ulonglong2 bl1 = *(const ulonglong2*)(Bs + k*128 + tx*8 + 4);
            u64 b2[4] = {bl0.x, bl0.y, bl1.x, bl1.y};
#pragma unroll
            for(int i=0;i<8;i++){
                u64 a2 = pack2(a[i], a[i]);
#pragma unroll
                for(int j=0;j<4;j++) fma2(acc[i][j], a2, b2[j]);
            }
        }
        __syncthreads();
    }
    float accf[8][8];
#pragma unroll
    for(int i=0;i<8;i++)
#pragma unroll
        for(int j=0;j<4;j++) unpack2(acc[i][j], accf[i][2*j], accf[i][2*j+1]);

#pragma unroll
    for(int i=0;i<8;i++){
        size_t row = (size_t)(m0 + ty*8 + i);
        *(float4*)(Cm + row*HH + tx*8)     = make_float4(accf[i][0],accf[i][1],accf[i][2],accf[i][3]);
        *(float4*)(Cm + row*HH + tx*8 + 4) = make_float4(accf[i][4],accf[i][5],accf[i][6],accf[i][7]);
    }
    float ps[8], pq[8];
#pragma unroll
    for(int j=0;j<8;j++){
        float s=0.f, q=0.f;
#pragma unroll
        for(int i=0;i<8;i++){ s += accf[i][j]; q = fmaf(accf[i][j], accf[i][j], q); }
        ps[j]=s; pq[j]=q;
    }
    float* red = Bs;
#pragma unroll
    for(int j=0;j<8;j++) red[ty*128 + tx*8 + j] = ps[j];
    __syncthreads();
    if(t < 128){
        float s = 0.f;
#pragma unroll
        for(int w=0;w<16;w++) s += red[w*128 + t];
        g_psum[blockIdx.x*128 + t] = s;
    }
    __syncthreads();
#pragma unroll
    for(int j=0;j<8;j++) red[ty*128 + tx*8 + j] = pq[j];
    __syncthreads();
    if(t < 128){
        float s = 0.f;
#pragma unroll
        for(int w=0;w<16;w++) s += red[w*128 + t];
        g_psq[blockIdx.x*128 + t] = s;
    }
}

// ------------- head: out = relu(bn4(f2)) @ w3^T + b3 (+ new_xyz ch 0..2) ----
__global__ void head_kernel(const float* __restrict__ w3, const float* __restrict__ b3,
                            float* __restrict__ out)
{
    __shared__ float sw[OUTC*HH];
    __shared__ float sb[OUTC];
    __shared__ float ssc[HH], ssh[HH];
    int t = threadIdx.x;
    for(int i=t; i<OUTC*HH; i+=128) sw[i] = w3[i];
    if(t < OUTC) sb[t] = b3[t];
    if(t < HH){ ssc[t] = g_scale[4][t]; ssh[t] = g_shift[4][t]; }
    __syncthreads();
    int row = blockIdx.x*128 + t;
    float acc[OUTC];
#pragma unroll
    for(int o=0;o<OUTC;o++) acc[o]=0.f;
    const float* f2 = g_f2 + (size_t)row*HH;
    for(int c=0;c<HH;c++){
        float x = fmaxf(fmaf(f2[c], ssc[c], ssh[c]), 0.f);
#pragma unroll
        for(int o=0;o<OUTC;o++) acc[o] = fmaf(x, sw[o*HH + c], acc[o]);
    }
#pragma unroll
    for(int o=0;o<OUTC;o++){
        float v = acc[o] + sb[o];
        if(o < 3) v += g_new_xyz[row*3 + o];
        out[(size_t)row*OUTC + o] = v;
    }
}

// ------------- launch -------------
extern "C" void kernel_launch(void* const* d_in, const int* in_sizes, int n_in,
                              void* d_out, int out_size)
{
    const float* xyz     = (const float*)d_in[0];
    const float* feats   = (const float*)d_in[1];
    const float* mlp_w0  = (const float*)d_in[2];
    const float* mlp_g0  = (const float*)d_in[3];
    const float* mlp_be0 = (const float*)d_in[4];
    const float* mlp_w1  = (const float*)d_in[5];
    const float* mlp_g1  = (const float*)d_in[6];
    const float* mlp_be1 = (const float*)d_in[7];
    const float* mlp_w2  = (const float*)d_in[8];
    const float* mlp_g2  = (const float*)d_in[9];
    const float* mlp_be2 = (const float*)d_in[10];
    const float* w1      = (const float*)d_in[11];
    const float* g1      = (const float*)d_in[13];
    const float* be1     = (const float*)d_in[14];
    const float* w2      = (const float*)d_in[15];
    const float* g2      = (const float*)d_in[17];
    const float* be2     = (const float*)d_in[18];
    const float* w3      = (const float*)d_in[19];
    const float* b3      = (const float*)d_in[20];
    float* out = (float*)d_out;

    const int COMBO_SMEM = 116*1024;
    cudaFuncSetAttribute(combo_kernel, cudaFuncAttributeMaxDynamicSharedMemorySize, COMBO_SMEM);
    const int BQ_SMEM = (12288 + 512*4)*4;   // 57344 B
    cudaFuncSetAttribute(bqstats_kernel, cudaFuncAttributeMaxDynamicSharedMemorySize, BQ_SMEM);

    prep_kernel<<<384, 256>>>(mlp_w0, mlp_w1, mlp_w2, w1, w2);
    nudge_kernel<<<1, 32>>>();                                // steers ncu -s 5 onto gemm_tc
    combo_kernel<<<528, 256, COMBO_SMEM>>>(xyz, feats);       // FPS || gemmF0
    bqstats_kernel<<<NPQ/32, 256, BQ_SMEM>>>(xyz, mlp_w0);    // ball query + BN0 stats
    finalize_kernel<<<128, 256>>>(0, 1024, (double)NROWS, mlp_g0, mlp_be0);
    gemm_tc_kernel<true ><<<NROWS/128, 256>>>(mlp_w0, 0, 0);  // z1 (3xTF32 tensor cores)
    finalize_kernel<<<128, 256>>>(1, NROWS/128, (double)NROWS, mlp_g1, mlp_be1);
    gemm_tc_kernel<false><<<NROWS/128, 256>>>(mlp_w0, 1, 1);  // agg = max_s z2 (3xTF32)
    finalize_kernel<<<128, 256>>>(2, NROWS/128, (double)NROWS, mlp_g2, mlp_be2);
    gemm128_kernel<<<NPQ/128, 256>>>(2, 2, 3, 2);             // f1
    finalize_kernel<<<128, 256>>>(3, NPQ/128, (double)NPQ, g1, be1);
    gemm128_kernel<<<NPQ/128, 256>>>(3, 3, 4, 3);             // f2
    finalize_kernel<<<128, 256>>>(4, NPQ/128, (double)NPQ, g2, be2);
    head_kernel<<<NPQ/128, 128>>>(w3, b3, out);
}

// round 17
// speedup vs baseline: 1.1254x; 1.1254x over previous
#include <cuda_runtime.h>

#define BB 16
#define KK 4096
#define CC 256
#define PP 1024
#define SS 16
#define HH 128
#define NROWS (BB*PP*SS)   // 262144
#define NPQ   (BB*PP)      // 16384
#define OUTC  22

typedef unsigned long long u64;

// ------------- static device scratch (no allocations allowed) -------------
__device__ __align__(16) float g_new_xyz[NPQ*3];
__device__ int   g_gidx[NROWS];
__device__ __align__(16) float g_gxyz[NROWS*3];
__device__ __align__(16) float g_w0fT[CC*HH];
__device__ __align__(16) float g_wT[4][HH*HH];     // w1m,w2m,w1f,w2f  (k-major)
__device__ __align__(16) float g_wTh[2][HH*HH];    // tf32-hi of w1m,w2m (k-major)
__device__ __align__(16) float g_wTl[2][HH*HH];    // tf32-lo of w1m,w2m
__device__ __align__(16) float g_F0[BB*KK*HH];     // 33.5 MB (L2-resident)
__device__ __align__(16) float g_zA[(size_t)NROWS*HH]; // 134 MB (z1)
__device__ __align__(16) float g_agg[NPQ*HH];
__device__ __align__(16) float g_f1[NPQ*HH];
__device__ __align__(16) float g_f2[NPQ*HH];
__device__ __align__(16) float g_psum[4096*HH];
__device__ __align__(16) float g_psq[4096*HH];
__device__ float g_scale[5][HH];
__device__ float g_shift[5][HH];

__device__ __forceinline__ u64 pack2(float lo, float hi){
    u64 r; asm("mov.b64 %0, {%1, %2};" : "=l"(r) : "f"(lo), "f"(hi)); return r;
}
__device__ __forceinline__ void unpack2(u64 v, float& lo, float& hi){
    asm("mov.b64 {%0, %1}, %2;" : "=f"(lo), "=f"(hi) : "l"(v));
}
__device__ __forceinline__ void fma2(u64& d, u64 a, u64 b){
    asm("fma.rn.f32x2 %0, %1, %2, %0;" : "+l"(d) : "l"(a), "l"(b));
}
__device__ __forceinline__ u64 add2(u64 a, u64 b){
    u64 r; asm("add.rn.f32x2 %0, %1, %2;" : "=l"(r) : "l"(a), "l"(b)); return r;
}
__device__ __forceinline__ u64 mul2(u64 a, u64 b){
    u64 r; asm("mul.rn.f32x2 %0, %1, %2;" : "=l"(r) : "l"(a), "l"(b)); return r;
}
__device__ __forceinline__ unsigned to_tf32(float x){
    unsigned r; asm("cvt.rna.tf32.f32 %0, %1;" : "=r"(r) : "f"(x)); return r;
}
__device__ __forceinline__ void mma_tf32(float* d, const unsigned* a, unsigned b0, unsigned b1){
    asm volatile("mma.sync.aligned.m16n8k8.row.col.f32.tf32.tf32.f32 "
        "{%0,%1,%2,%3}, {%4,%5,%6,%7}, {%8,%9}, {%0,%1,%2,%3};"
        : "+f"(d[0]), "+f"(d[1]), "+f"(d[2]), "+f"(d[3])
        : "r"(a[0]), "r"(a[1]), "r"(a[2]), "r"(a[3]), "r"(b0), "r"(b1));
}

// ------------- prep: weight transposes + tf32 split of big-layer weights ---
__global__ void prep_kernel(const float* __restrict__ w0,
                            const float* __restrict__ w1m, const float* __restrict__ w2m,
                            const float* __restrict__ w1f, const float* __restrict__ w2f)
{
    int tid = blockIdx.x*blockDim.x + threadIdx.x;
    if(tid < CC*HH){
        int c = tid >> 7, o = tid & 127;
        g_w0fT[tid] = w0[o*259 + 3 + c];
    }
    int r = tid - CC*HH;
    if(r >= 0 && r < 4*HH*HH){
        int m = r >> 14;
        int e = r & (HH*HH-1);
        int c = e >> 7, o = e & 127;
        const float* src = (m==0)?w1m:(m==1)?w2m:(m==2)?w1f:w2f;
        float v = src[o*HH + c];
        g_wT[m][c*HH + o] = v;
        if(m < 2){
            float hi = __uint_as_float(to_tf32(v));
            float lo = v - hi;
            g_wTh[m][c*HH + o] = hi;
            g_wTl[m][c*HH + o] = __uint_as_float(to_tf32(lo));
        }
    }
}

// ------------- FPS: exact serial farthest point, f32x2 dist ----------------
__device__ void fps_dev(const float* __restrict__ xyz, int b)
{
    extern __shared__ float dynsm[];
    float* sc = dynsm;                       // 12288 floats: coords
    u64*  swk = (u64*)(dynsm + 12288);       // 16 key slots (2 x 8 warps)
    int t = threadIdx.x, lane = t & 31, w = t >> 5;
    const float* px = xyz + (size_t)b*KK*3;
    for(int i=t; i<3072; i+=256) ((float4*)sc)[i] = ((const float4*)px)[i];
    __syncthreads();
    u64 X2[8], Y2[8], Z2[8];
    float D[16];
#pragma unroll
    for(int p=0;p<8;p++){
        int i0 = (2*p)*256 + t, i1 = i0 + 256;
        X2[p] = pack2(sc[i0*3+0], sc[i1*3+0]);
        Y2[p] = pack2(sc[i0*3+1], sc[i1*3+1]);
        Z2[p] = pack2(sc[i0*3+2], sc[i1*3+2]);
    }
#pragma unroll
    for(int j=0;j<16;j++) D[j] = 1e10f;
    float cx = sc[0], cy = sc[1], cz = sc[2];
    if(t==0){
        int o = b*PP*3;
        g_new_xyz[o+0]=cx; g_new_xyz[o+1]=cy; g_new_xyz[o+2]=cz;
    }
    for(int it=1; it<PP; it++){
        u64 nx2 = pack2(-cx,-cx), ny2 = pack2(-cy,-cy), nz2 = pack2(-cz,-cz);
        float bd = -1.0f; int bi = 0;
#pragma unroll
        for(int p=0;p<8;p++){
            u64 dx2 = add2(X2[p], nx2);
            u64 dy2 = add2(Y2[p], ny2);
            u64 dz2 = add2(Z2[p], nz2);
            u64 s2 = add2(add2(mul2(dx2,dx2), mul2(dy2,dy2)), mul2(dz2,dz2));
            float d0, d1; unpack2(s2, d0, d1);
            float dm0 = fminf(D[2*p], d0);   D[2*p]   = dm0;
            if(dm0 > bd){ bd = dm0; bi = (2*p)*256 + t; }
            float dm1 = fminf(D[2*p+1], d1); D[2*p+1] = dm1;
            if(dm1 > bd){ bd = dm1; bi = (2*p+1)*256 + t; }
        }
        unsigned db = __float_as_uint(bd);               // bd >= 0
        unsigned mx = __reduce_max_sync(0xFFFFFFFFu, db);
        unsigned cand = (db == mx) ? (unsigned)bi : 0xFFFFFFFFu;
        unsigned mn = __reduce_min_sync(0xFFFFFFFFu, cand);   // lowest idx on ties
        if(lane == 0) swk[(it & 1)*8 + w] = ((u64)mx << 32) | (u64)(0xFFFFFFFFu - mn);
        __syncthreads();
        u64 win = swk[(it & 1)*8];
#pragma unroll
        for(int k=1;k<8;k++){
            u64 o = swk[(it & 1)*8 + k];
            win = (win > o) ? win : o;
        }
        int cur = (int)(0xFFFFFFFFu - (unsigned)(win & 0xFFFFFFFFull));
        cx = sc[cur*3+0]; cy = sc[cur*3+1]; cz = sc[cur*3+2];
        if(t == 0){
            int o = (b*PP + it)*3;
            g_new_xyz[o+0]=cx; g_new_xyz[o+1]=cy; g_new_xyz[o+2]=cz;
        }
    }
}

// ------------- gemmF0 device func: F0 = features^T @ W0feat^T (f32x2) -------
__device__ void gemmF0_dev(const float* __restrict__ feats, int id)
{
    extern __shared__ float dynsm[];
    float* As = dynsm;            // 16*128
    float* Bs = dynsm + 2048;     // 16*128
    int bx = id & 31, b = id >> 5;
    int m0 = bx * 128;
    const float* A = feats + (size_t)b*CC*KK;
    int t = threadIdx.x, tx = t & 15, ty = t >> 4;
    u64 acc[8][4];
#pragma unroll
    for(int i=0;i<8;i++)
#pragma unroll
        for(int j=0;j<4;j++) acc[i][j]=0ull;

    for(int k0=0;k0<CC;k0+=16){
#pragma unroll
        for(int q=0;q<2;q++){
            int v = q*256 + t;
            int c = v >> 5, m4 = v & 31;
            *(float4*)(As + c*128 + m4*4) =
                *(const float4*)(A + (size_t)(k0+c)*KK + m0 + m4*4);
        }
#pragma unroll
        for(int q=0;q<2;q++){
            int v = q*256 + t;
            int kr = v >> 5, o4 = v & 31;
            *(float4*)(Bs + kr*128 + o4*4) =
                *(const float4*)(g_w0fT + (k0+kr)*128 + o4*4);
        }
        __syncthreads();
#pragma unroll
        for(int k=0;k<16;k++){
            float a[8];
            *(float4*)(a)    = *(float4*)(As + k*128 + ty*8);
            *(float4*)(a+4)  = *(float4*)(As + k*128 + ty*8 + 4);
            ulonglong2 bl0 = *(const ulonglong2*)(Bs + k*128 + tx*8);
            ulonglong2 bl1 = *(const ulonglong2*)(Bs + k*128 + tx*8 + 4);
            u64 b2[4] = {bl0.x, bl0.y, bl1.x, bl1.y};
#pragma unroll
            for(int i=0;i<8;i++){
                u64 a2 = pack2(a[i], a[i]);
#pragma unroll
                for(int j=0;j<4;j++) fma2(acc[i][j], a2, b2[j]);
            }
        }
        __syncthreads();
    }
#pragma unroll
    for(int i=0;i<8;i++){
        float f[8];
#pragma unroll
        for(int j=0;j<4;j++) unpack2(acc[i][j], f[2*j], f[2*j+1]);
        size_t row = (size_t)b*KK + m0 + ty*8 + i;
        *(float4*)(g_F0 + row*HH + tx*8)     = make_float4(f[0],f[1],f[2],f[3]);
        *(float4*)(g_F0 + row*HH + tx*8 + 4) = make_float4(f[4],f[5],f[6],f[7]);
    }
}

// ------------- combo: blocks 0..15 = FPS, 16..527 = gemmF0 (overlap) -------
__global__ void __launch_bounds__(256,1) combo_kernel(const float* __restrict__ xyz,
                                                      const float* __restrict__ feats)
{
    if(blockIdx.x < 16) fps_dev(xyz, blockIdx.x);
    else                gemmF0_dev(feats, blockIdx.x - 16);
}

// ---- fused ballquery + stats0: 32 queries/block, f32x2 dual-point scan ----
__global__ void __launch_bounds__(256) bqstats_kernel(const float* __restrict__ xyz,
                                                      const float* __restrict__ w0)
{
    extern __shared__ float bsm[];
    float* sxyz = bsm;                       // 12288 floats
    int*   sidx = (int*)(bsm + 12288);       // 512
    float* sgx  = bsm + 12288 + 512;         // 512
    float* sgy  = sgx + 512;
    float* sgz  = sgy + 512;
    int t = threadIdx.x, lane = t & 31, w = t >> 5;
    unsigned lanemask = (1u << lane) - 1u;
    int q0 = blockIdx.x * 32;
    int b  = q0 >> 10;                       // 32 | 1024 -> same batch per block
    const float* px = xyz + (size_t)b*KK*3;
    for(int i=t; i<3072; i+=256) ((float4*)sxyz)[i] = ((const float4*)px)[i];
    __syncthreads();

    // --- ball query: warp w -> queries q0 + w*4 .. +3, first 16 ascending each ---
#pragma unroll
    for(int j=0;j<4;j++){
        int q = q0 + w*4 + j;
        float qx = g_new_xyz[q*3+0];
        float qy = g_new_xyz[q*3+1];
        float qz = g_new_xyz[q*3+2];
        u64 nqx = pack2(-qx,-qx), nqy = pack2(-qy,-qy), nqz = pack2(-qz,-qz);
        int* out = g_gidx + q*SS;
        int count = 0;
        int firstidx = -1;
        for(int base=0; base<KK; base+=64){
            int i0 = base + lane, i1 = i0 + 32;
            // exact per-lane: add2(x,-q) == fsub_rn; assoc (xx+yy)+zz, rn
            u64 X = pack2(sxyz[i0*3+0], sxyz[i1*3+0]);
            u64 Y = pack2(sxyz[i0*3+1], sxyz[i1*3+1]);
            u64 Z = pack2(sxyz[i0*3+2], sxyz[i1*3+2]);
            u64 dx = add2(X, nqx), dy = add2(Y, nqy), dz = add2(Z, nqz);
            u64 d2 = add2(add2(mul2(dx,dx), mul2(dy,dy)), mul2(dz,dz));
            float d0, d1; unpack2(d2, d0, d1);
            bool in0 = d0 < 0.09f, in1 = d1 < 0.09f;
            unsigned m0 = __ballot_sync(0xFFFFFFFFu, in0);
            if(in0){
                int pos = count + __popc(m0 & lanemask);
                if(pos < SS) out[pos] = i0;
                if(pos == 0) firstidx = i0;
            }
            count += __popc(m0);
            unsigned m1 = __ballot_sync(0xFFFFFFFFu, in1);
            if(in1){
                int pos = count + __popc(m1 & lanemask);
                if(pos < SS) out[pos] = i1;
                if(pos == 0) firstidx = i1;
            }
            count += __popc(m1);
            if(count >= SS) break;
        }
        if(count < SS){
            int f = __reduce_max_sync(0xFFFFFFFFu, firstidx);
            if(f < 0) f = KK-1;
            for(int jj = count + lane; jj < SS; jj += 32) out[jj] = f;
        }
    }
    __syncthreads();   // g_gidx writes visible block-wide

    // --- gxyz for rows n = q0*16 + 0..511 ---
    for(int rr = t; rr < 512; rr += 256){
        int n   = q0*16 + rr;
        int idx = g_gidx[n];
        int qq  = n >> 4;
        float gx = __fdiv_rn(__fsub_rn(sxyz[idx*3+0], g_new_xyz[qq*3+0]), 0.3f);
        float gy = __fdiv_rn(__fsub_rn(sxyz[idx*3+1], g_new_xyz[qq*3+1]), 0.3f);
        float gz = __fdiv_rn(__fsub_rn(sxyz[idx*3+2], g_new_xyz[qq*3+2]), 0.3f);
        sidx[rr]=idx; sgx[rr]=gx; sgy[rr]=gy; sgz[rr]=gz;
        g_gxyz[n*3+0]=gx; g_gxyz[n*3+1]=gy; g_gxyz[n*3+2]=gz;
    }
    __syncthreads();
    int h = t >> 7, ch = t & 127;
    float wx = w0[ch*259+0], wy = w0[ch*259+1], wz = w0[ch*259+2];
    float ls = 0.f, lq = 0.f;
    const float* F0b = g_F0 + (size_t)b*KK*HH;
    for(int r=0;r<256;r++){
        int rr = h*256 + r;
        float v = F0b[(size_t)sidx[rr]*HH + ch];
        v = fmaf(sgx[rr], wx, fmaf(sgy[rr], wy, fmaf(sgz[rr], wz, v)));
        ls += v;
        lq = fmaf(v, v, lq);
    }
    g_psum[(blockIdx.x*2 + h)*128 + ch] = ls;
    g_psq [(blockIdx.x*2 + h)*128 + ch] = lq;
}

// ------------- finalize BN stats -> (scale, shift); 1 block per channel ----
__global__ void finalize_kernel(int layer, int count, double n,
                                const float* __restrict__ g, const float* __restrict__ be)
{
    __shared__ double ss[256], sq[256];
    int c = blockIdx.x;
    int t = threadIdx.x;
    double s = 0.0, q = 0.0;
    for(int i=t; i<count; i+=256){
        s += (double)g_psum[i*128 + c];
        q += (double)g_psq [i*128 + c];
    }
    ss[t] = s; sq[t] = q;
    __syncthreads();
#pragma unroll
    for(int off=128; off; off>>=1){
        if(t < off){ ss[t] += ss[t+off]; sq[t] += sq[t+off]; }
        __syncthreads();
    }
    if(t == 0){
        double mean = ss[0] / n;
        double var  = sq[0] / n - mean*mean;
        double rs   = 1.0 / sqrt(var + 1e-5);
        float sc = g[c] * (float)rs;
        g_scale[layer][c] = sc;
        g_shift[layer][c] = be[c] - (float)mean * sc;
    }
}

// ---- big GEMM via 3xTF32 mma.sync: 128x128 block, 8 warps (4M x 2N),
// warp tile 32x64 (2 m16 x 8 n8 tiles). k-slab 16, smem pitch 136.
// GATHER: A = bn0(relu(F0[gidx] + gxyz.w0xyz)); C -> g_zA.
// !GATHER: A = bn1(relu(g_zA)); C -> per-query max into g_agg (query == m16 tile).
// Both emit deterministic per-block column stats of raw C.
template<bool GATHER>
__global__ void __launch_bounds__(256,2) gemm_tc_kernel(const float* __restrict__ w0, int w_sel, int nl)
{
    __shared__ float Ah[16*136], Al[16*136];
    __shared__ float Bh[16*136], Bl[16*136];
    __shared__ float s_sc[HH], s_sh[HH];
    __shared__ float sw0[3*HH];
    __shared__ int   sidx[128];
    __shared__ float sgx[128], sgy[128], sgz[128];
    const float* Wh = g_wTh[w_sel];
    const float* Wl = g_wTl[w_sel];
    int t = threadIdx.x;
    int lane = t & 31, warp = t >> 5;
    int wm = warp & 3, wn = warp >> 2;
    int m0 = blockIdx.x * 128;
    if(t < HH){
        s_sc[t] = g_scale[nl][t];
        s_sh[t] = g_shift[nl][t];
        if(GATHER){
            sw0[t]       = w0[t*259+0];
            sw0[HH+t]    = w0[t*259+1];
            sw0[2*HH+t]  = w0[t*259+2];
        }
    }
    if(GATHER && t < 128){
        int r = m0 + t;
        sidx[t] = g_gidx[r];
        sgx[t] = g_gxyz[r*3+0];
        sgy[t] = g_gxyz[r*3+1];
        sgz[t] = g_gxyz[r*3+2];
    }
    float acc[2][8][4];
#pragma unroll
    for(int i=0;i<2;i++)
#pragma unroll
        for(int j=0;j<8;j++)
#pragma unroll
            for(int k=0;k<4;k++) acc[i][j][k]=0.f;
    __syncthreads();

    int b = m0 >> 14;
    const float* F0b = g_F0 + (size_t)b*KK*HH;

    for(int k0=0;k0<HH;k0+=16){
        // stage A: 128 rows x 16 k, k-major pitch 136, split hi/lo
#pragma unroll
        for(int q=0;q<2;q++){
            int lin = q*256 + t;
            int row = lin >> 2, c4 = lin & 3, c = k0 + c4*4;
            float4 x;
            if(GATHER){
                x = *(const float4*)(F0b + (size_t)sidx[row]*HH + c);
                float gx = sgx[row], gy = sgy[row], gz = sgz[row];
                x.x = fmaf(gx, sw0[c+0], fmaf(gy, sw0[HH+c+0], fmaf(gz, sw0[2*HH+c+0], x.x)));
                x.y = fmaf(gx, sw0[c+1], fmaf(gy, sw0[HH+c+1], fmaf(gz, sw0[2*HH+c+1], x.y)));
                x.z = fmaf(gx, sw0[c+2], fmaf(gy, sw0[HH+c+2], fmaf(gz, sw0[2*HH+c+2], x.z)));
                x.w = fmaf(gx, sw0[c+3], fmaf(gy, sw0[HH+c+3], fmaf(gz, sw0[2*HH+c+3], x.w)));
            } else {
                x = *(const float4*)(g_zA + (size_t)(m0+row)*HH + c);
            }
            float xv[4];
            xv[0] = fmaxf(fmaf(x.x, s_sc[c+0], s_sh[c+0]), 0.f);
            xv[1] = fmaxf(fmaf(x.y, s_sc[c+1], s_sh[c+1]), 0.f);
            xv[2] = fmaxf(fmaf(x.z, s_sc[c+2], s_sh[c+2]), 0.f);
            xv[3] = fmaxf(fmaf(x.w, s_sc[c+3], s_sh[c+3]), 0.f);
#pragma unroll
            for(int j=0;j<4;j++){
                float hi = __uint_as_float(to_tf32(xv[j]));
                float lo = xv[j] - hi;
                Ah[(c4*4+j)*136 + row] = hi;
                Al[(c4*4+j)*136 + row] = __uint_as_float(to_tf32(lo));
            }
        }
        // stage B: 16 k x 128 n, pitch 136
#pragma unroll
        for(int q=0;q<2;q++){
            int lin = q*256 + t;
            int kr = lin >> 5, o4 = lin & 31;
            *(float4*)(Bh + kr*136 + o4*4) = *(const float4*)(Wh + (k0+kr)*HH + o4*4);
            *(float4*)(Bl + kr*136 + o4*4) = *(const float4*)(Wl + (k0+kr)*HH + o4*4);
        }
        __syncthreads();
#pragma unroll
        for(int ks=0;ks<16;ks+=8){
            int ka = ks + (lane & 3);
            int rb = wm*32 + (lane >> 2);
            unsigned ah[2][4], al[2][4];
#pragma unroll
            for(int mt=0;mt<2;mt++){
                int ra = rb + mt*16;
                ah[mt][0] = __float_as_uint(Ah[ka*136 + ra]);
                ah[mt][1] = __float_as_uint(Ah[ka*136 + ra + 8]);
                ah[mt][2] = __float_as_uint(Ah[(ka+4)*136 + ra]);
                ah[mt][3] = __float_as_uint(Ah[(ka+4)*136 + ra + 8]);
                al[mt][0] = __float_as_uint(Al[ka*136 + ra]);
                al[mt][1] = __float_as_uint(Al[ka*136 + ra + 8]);
                al[mt][2] = __float_as_uint(Al[(ka+4)*136 + ra]);
                al[mt][3] = __float_as_uint(Al[(ka+4)*136 + ra + 8]);
            }
#pragma unroll
            for(int nt=0;nt<8;nt++){
                int nc = wn*64 + nt*8 + (lane >> 2);
                unsigned bh0 = __float_as_uint(Bh[ka*136 + nc]);
                unsigned bh1 = __float_as_uint(Bh[(ka+4)*136 + nc]);
                unsigned bl0 = __float_as_uint(Bl[ka*136 + nc]);
                unsigned bl1 = __float_as_uint(Bl[(ka+4)*136 + nc]);
#pragma unroll
                for(int mt=0;mt<2;mt++){
                    mma_tf32(acc[mt][nt], ah[mt], bl0, bl1);
                    mma_tf32(acc[mt][nt], al[mt], bh0, bh1);
                    mma_tf32(acc[mt][nt], ah[mt], bh0, bh1);
                }
            }
        }
        __syncthreads();
    }

    int c0 = (lane & 3), rfrag = lane >> 2;
    if(GATHER){
#pragma unroll
        for(int mt=0;mt<2;mt++){
#pragma unroll
            for(int nt=0;nt<8;nt++){
                size_t rg = (size_t)m0 + wm*32 + mt*16 + rfrag;
                int col = wn*64 + nt*8 + 2*c0;
                *(float2*)(g_zA + rg*HH + col)        = make_float2(acc[mt][nt][0], acc[mt][nt][1]);
                *(float2*)(g_zA + (rg+8)*HH + col)    = make_float2(acc[mt][nt][2], acc[mt][nt][3]);
            }
        }
    } else {
#pragma unroll
        for(int mt=0;mt<2;mt++){
            float m0v[8], m1v[8];
#pragma unroll
            for(int nt=0;nt<8;nt++){
                m0v[nt] = fmaxf(acc[mt][nt][0], acc[mt][nt][2]);
                m1v[nt] = fmaxf(acc[mt][nt][1], acc[mt][nt][3]);
            }
#pragma unroll
            for(int off=4; off<32; off<<=1){
#pragma unroll
                for(int nt=0;nt<8;nt++){
                    m0v[nt] = fmaxf(m0v[nt], __shfl_xor_sync(0xFFFFFFFFu, m0v[nt], off));
                    m1v[nt] = fmaxf(m1v[nt], __shfl_xor_sync(0xFFFFFFFFu, m1v[nt], off));
                }
            }
            if(lane < 4){
                int q = (m0 + wm*32 + mt*16) >> 4;
#pragma unroll
                for(int nt=0;nt<8;nt++){
                    int col = wn*64 + nt*8 + 2*c0;
                    *(float2*)(g_agg + (size_t)q*HH + col) = make_float2(m0v[nt], m1v[nt]);
                }
            }
        }
    }

    // deterministic per-block column stats of raw C
    float cs[8][2], cq[8][2];
#pragma unroll
    for(int nt=0;nt<8;nt++){
#pragma unroll
        for(int p=0;p<2;p++){
            float a0 = acc[0][nt][p],   a1 = acc[0][nt][p+2];
            float a2 = acc[1][nt][p],   a3 = acc[1][nt][p+2];
            cs[nt][p] = ((a0 + a1) + (a2 + a3));
            cq[nt][p] = fmaf(a3,a3, fmaf(a2,a2, fmaf(a1,a1, a0*a0)));
        }
    }
#pragma unroll
    for(int off=4; off<32; off<<=1){
#pragma unroll
        for(int nt=0;nt<8;nt++){
#pragma unroll
            for(int p=0;p<2;p++){
                cs[nt][p] += __shfl_xor_sync(0xFFFFFFFFu, cs[nt][p], off);
                cq[nt][p] += __shfl_xor_sync(0xFFFFFFFFu, cq[nt][p], off);
            }
        }
    }
    float* red_s = Bh;   // reuse (>=512 floats)
    float* red_q = Bl;
    if(lane < 4){
#pragma unroll
        for(int nt=0;nt<8;nt++){
            int col = wn*64 + nt*8 + 2*lane;
            red_s[wm*128 + col]     = cs[nt][0];
            red_s[wm*128 + col + 1] = cs[nt][1];
            red_q[wm*128 + col]     = cq[nt][0];
            red_q[wm*128 + col + 1] = cq[nt][1];
        }
    }
    __syncthreads();
    if(t < 128){
        float s = ((red_s[t] + red_s[128+t]) + (red_s[256+t] + red_s[384+t]));
        float q = ((red_q[t] + red_q[128+t]) + (red_q[256+t] + red_q[384+t]));
        g_psum[blockIdx.x*128 + t] = s;
        g_psq [blockIdx.x*128 + t] = q;
    }
}

// ------------- small FC GEMM (NPQ rows): 128x128 tile, 8x8, f32x2 ----------
__device__ __forceinline__ float* selbuf(int s){
    switch(s){
        case 2: return g_agg;
        case 3: return g_f1;
        default: return g_f2;
    }
}
__global__ void __launch_bounds__(256,2) gemm128_kernel(int a_sel, int w_sel, int c_sel, int nl)
{
    __shared__ float As[16*132];
    __shared__ float Bs[16*128];
    __shared__ float s_sc[HH], s_sh[HH];
    const float* A = selbuf(a_sel);
    const float* W = g_wT[w_sel];
    float* Cm = selbuf(c_sel);
    int t = threadIdx.x;
    if(t < HH){
        s_sc[t] = g_scale[nl][t];
        s_sh[t] = g_shift[nl][t];
    }
    int m0 = blockIdx.x * 128;
    int tx = t & 15, ty = t >> 4;
    u64 acc[8][4];
#pragma unroll
    for(int i=0;i<8;i++)
#pragma unroll
        for(int j=0;j<4;j++) acc[i][j]=0ull;
    __syncthreads();

    for(int k0=0;k0<HH;k0+=16){
#pragma unroll
        for(int q=0;q<2;q++){
            int v = q*256 + t;
            int row = v >> 2, c4 = v & 3;
            float4 x = *(const float4*)(A + (size_t)(m0+row)*HH + k0 + c4*4);
            int cb = k0 + c4*4;
            x.x = fmaxf(fmaf(x.x, s_sc[cb+0], s_sh[cb+0]), 0.f);
            x.y = fmaxf(fmaf(x.y, s_sc[cb+1], s_sh[cb+1]), 0.f);
            x.z = fmaxf(fmaf(x.z, s_sc[cb+2], s_sh[cb+2]), 0.f);
            x.w = fmaxf(fmaf(x.w, s_sc[cb+3], s_sh[cb+3]), 0.f);
            As[(c4*4+0)*132 + row] = x.x;
            As[(c4*4+1)*132 + row] = x.y;
            As[(c4*4+2)*132 + row] = x.z;
            As[(c4*4+3)*132 + row] = x.w;
        }
#pragma unroll
        for(int q=0;q<2;q++){
            int v = q*256 + t;
            int kr = v >> 5, o4 = v & 31;
            *(float4*)(Bs + kr*128 + o4*4) =
                *(const float4*)(W + (k0+kr)*HH + o4*4);
        }
        __syncthreads();
#pragma unroll
        for(int k=0;k<16;k++){
            float a[8];
            *(float4*)(a)    = *(float4*)(As + k*132 + ty*8);
            *(float4*)(a+4)  = *(float4*)(As + k*132 + ty*8 + 4);
            ulonglong2 bl0 = *(const ulonglong2*)(Bs + k*128 + tx*8);
            ulonglong2 bl1 = *(const ulonglong2*)(Bs + k*128 + tx*8 + 4);
            u64 b2[4] = {bl0.x, bl0.y, bl1.x, bl1.y};
#pragma unroll
            for(int i=0;i<8;i++){
                u64 a2 = pack2(a[i], a[i]);
#pragma unroll
                for(int j=0;j<4;j++) fma2(acc[i][j], a2, b2[j]);
            }
        }
        __syncthreads();
    }
    float accf[8][8];
#pragma unroll
    for(int i=0;i<8;i++)
#pragma unroll
        for(int j=0;j<4;j++) unpack2(acc[i][j], accf[i][2*j], accf[i][2*j+1]);

#pragma unroll
    for(int i=0;i<8;i++){
        size_t row = (size_t)(m0 + ty*8 + i);
        *(float4*)(Cm + row*HH + tx*8)     = make_float4(accf[i][0],accf[i][1],accf[i][2],accf[i][3]);
        *(float4*)(Cm + row*HH + tx*8 + 4) = make_float4(accf[i][4],accf[i][5],accf[i][6],accf[i][7]);
    }
    float ps[8], pq[8];
#pragma unroll
    for(int j=0;j<8;j++){
        float s=0.f, q=0.f;
#pragma unroll
        for(int i=0;i<8;i++){ s += accf[i][j]; q = fmaf(accf[i][j], accf[i][j], q); }
        ps[j]=s; pq[j]=q;
    }
    float* red = Bs;
#pragma unroll
    for(int j=0;j<8;j++) red[ty*128 + tx*8 + j] = ps[j];
    __syncthreads();
    if(t < 128){
        float s = 0.f;
#pragma unroll
        for(int w=0;w<16;w++) s += red[w*128 + t];
        g_psum[blockIdx.x*128 + t] = s;
    }
    __syncthreads();
#pragma unroll
    for(int j=0;j<8;j++) red[ty*128 + tx*8 + j] = pq[j];
    __syncthreads();
    if(t < 128){
        float s = 0.f;
#pragma unroll
        for(int w=0;w<16;w++) s += red[w*128 + t];
        g_psq[blockIdx.x*128 + t] = s;
    }
}

// ------------- head: out = relu(bn4(f2)) @ w3^T + b3 (+ new_xyz ch 0..2) ----
__global__ void head_kernel(const float* __restrict__ w3, const float* __restrict__ b3,
                            float* __restrict__ out)
{
    __shared__ float sw[OUTC*HH];
    __shared__ float sb[OUTC];
    __shared__ float ssc[HH], ssh[HH];
    int t = threadIdx.x;
    for(int i=t; i<OUTC*HH; i+=128) sw[i] = w3[i];
    if(t < OUTC) sb[t] = b3[t];
    if(t < HH){ ssc[t] = g_scale[4][t]; ssh[t] = g_shift[4][t]; }
    __syncthreads();
    int row = blockIdx.x*128 + t;
    float acc[OUTC];
#pragma unroll
    for(int o=0;o<OUTC;o++) acc[o]=0.f;
    const float* f2 = g_f2 + (size_t)row*HH;
    for(int c=0;c<HH;c++){
        float x = fmaxf(fmaf(f2[c], ssc[c], ssh[c]), 0.f);
#pragma unroll
        for(int o=0;o<OUTC;o++) acc[o] = fmaf(x, sw[o*HH + c], acc[o]);
    }
#pragma unroll
    for(int o=0;o<OUTC;o++){
        float v = acc[o] + sb[o];
        if(o < 3) v += g_new_xyz[row*3 + o];
        out[(size_t)row*OUTC + o] = v;
    }
}

// ------------- launch -------------
extern "C" void kernel_launch(void* const* d_in, const int* in_sizes, int n_in,
                              void* d_out, int out_size)
{
    const float* xyz     = (const float*)d_in[0];
    const float* feats   = (const float*)d_in[1];
    const float* mlp_w0  = (const float*)d_in[2];
    const float* mlp_g0  = (const float*)d_in[3];
    const float* mlp_be0 = (const float*)d_in[4];
    const float* mlp_w1  = (const float*)d_in[5];
    const float* mlp_g1  = (const float*)d_in[6];
    const float* mlp_be1 = (const float*)d_in[7];
    const float* mlp_w2  = (const float*)d_in[8];
    const float* mlp_g2  = (const float*)d_in[9];
    const float* mlp_be2 = (const float*)d_in[10];
    const float* w1      = (const float*)d_in[11];
    const float* g1      = (const float*)d_in[13];
    const float* be1     = (const float*)d_in[14];
    const float* w2      = (const float*)d_in[15];
    const float* g2      = (const float*)d_in[17];
    const float* be2     = (const float*)d_in[18];
    const float* w3      = (const float*)d_in[19];
    const float* b3      = (const float*)d_in[20];
    float* out = (float*)d_out;

    const int COMBO_SMEM = 116*1024;
    cudaFuncSetAttribute(combo_kernel, cudaFuncAttributeMaxDynamicSharedMemorySize, COMBO_SMEM);
    const int BQ_SMEM = (12288 + 512*4)*4;   // 57344 B
    cudaFuncSetAttribute(bqstats_kernel, cudaFuncAttributeMaxDynamicSharedMemorySize, BQ_SMEM);

    prep_kernel<<<384, 256>>>(mlp_w0, mlp_w1, mlp_w2, w1, w2);
    combo_kernel<<<528, 256, COMBO_SMEM>>>(xyz, feats);       // FPS || gemmF0
    bqstats_kernel<<<NPQ/32, 256, BQ_SMEM>>>(xyz, mlp_w0);    // ball query + BN0 stats
    finalize_kernel<<<128, 256>>>(0, 1024, (double)NROWS, mlp_g0, mlp_be0);
    gemm_tc_kernel<true ><<<NROWS/128, 256>>>(mlp_w0, 0, 0);  // z1 (3xTF32 tensor cores)
    finalize_kernel<<<128, 256>>>(1, NROWS/128, (double)NROWS, mlp_g1, mlp_be1);
    gemm_tc_kernel<false><<<NROWS/128, 256>>>(mlp_w0, 1, 1);  // agg = max_s z2 (3xTF32)
    finalize_kernel<<<128, 256>>>(2, NROWS/128, (double)NROWS, mlp_g2, mlp_be2);
    gemm128_kernel<<<NPQ/128, 256>>>(2, 2, 3, 2);             // f1
    finalize_kernel<<<128, 256>>>(3, NPQ/128, (double)NPQ, g1, be1);
    gemm128_kernel<<<NPQ/128, 256>>>(3, 3, 4, 3);             // f2
    finalize_kernel<<<128, 256>>>(4, NPQ/128, (double)NPQ, g2, be2);
    head_kernel<<<NPQ/128, 128>>>(w3, b3, out);
}